// round 12
// baseline (speedup 1.0000x reference)
#include <cuda_runtime.h>
#include <cstddef>
#include <cstdint>

#define H    400
#define CC   4
#define NN   16
#define OO   32
#define RR   4
#define HH   (H*H)          // 160000

// Static device scratch
__device__ float g_T [(size_t)OO*CC*HH];   // 81.92 MB : T[o][c][i][j]
__device__ float g_XT[(size_t)NN*CC*HH];   // 40.96 MB : XT[n][c][j][k]
__device__ float g_rows[NN*OO*H];
__device__ float g_cols[NN*OO*H];

// ---- cp.async helpers ------------------------------------------------------
__device__ __forceinline__ void cp16(void* smem_dst, const void* gmem_src) {
    uint32_t d = (uint32_t)__cvta_generic_to_shared(smem_dst);
    asm volatile("cp.async.cg.shared.global [%0], [%1], 16;\n" :: "r"(d), "l"(gmem_src));
}
__device__ __forceinline__ void cp_commit() {
    asm volatile("cp.async.commit_group;\n");
}
template<int N>
__device__ __forceinline__ void cp_wait() {
    asm volatile("cp.async.wait_group %0;\n" :: "n"(N));
}
__device__ __forceinline__ float dot4(float4 a, float4 b) {
    return a.x*b.x + a.y*b.y + a.z*b.z + a.w*b.w;
}

// ---------------------------------------------------------------------------
// Kernel 1a: T[o,c,i,j] = sum_r L[o,c,i,r]*L[o,c,j,r].  grid=(128,16), blk 256
// ---------------------------------------------------------------------------
__global__ __launch_bounds__(256)
void kT(const float* __restrict__ L, float* __restrict__ T)
{
    const int s = blockIdx.x;                 // o*CC + c
    const float* Lp = L + (size_t)s * (H*RR);
    float*       Tp = T + (size_t)s * HH;

    __shared__ float sL[H*RR];
    for (int idx = threadIdx.x; idx < H*RR; idx += 256) sL[idx] = Lp[idx];
    __syncthreads();

    const int base = blockIdx.y * 625;
    for (int loc = threadIdx.x; loc < 625; loc += 256) {
        const int item = base + loc;
        const int it = item / 100;
        const int jq = item % 100;
        const int i0 = it * 4, j0 = jq * 4;

        float4 li[4], lj[4];
        #pragma unroll
        for (int d = 0; d < 4; d++) {
            li[d] = *reinterpret_cast<const float4*>(&sL[(i0 + d) * 4]);
            lj[d] = *reinterpret_cast<const float4*>(&sL[(j0 + d) * 4]);
        }
        #pragma unroll
        for (int d = 0; d < 4; d++) {
            float4 v;
            v.x = dot4(li[d], lj[0]);
            v.y = dot4(li[d], lj[1]);
            v.z = dot4(li[d], lj[2]);
            v.w = dot4(li[d], lj[3]);
            *reinterpret_cast<float4*>(&Tp[(size_t)(i0 + d) * H + j0]) = v;
        }
    }
}

// ---------------------------------------------------------------------------
// Kernel 1b: per-(n,c) transpose XT[j,k] = x[k,j].  grid=(13,13,64), blk 256 flat
// ---------------------------------------------------------------------------
__global__ __launch_bounds__(256)
void kTrans(const float* __restrict__ X, float* __restrict__ XT)
{
    __shared__ float t[32][33];
    const int s = blockIdx.z;
    const float* src = X  + (size_t)s * HH;
    float*       dst = XT + (size_t)s * HH;
    const int tx = threadIdx.x & 31;
    const int ty = threadIdx.x >> 5;

    const int j = blockIdx.x * 32 + tx;
    #pragma unroll
    for (int m = 0; m < 32; m += 8) {
        const int k = blockIdx.y * 32 + ty + m;
        if (k < H && j < H)
            t[ty + m][tx] = src[(size_t)k * H + j];
    }
    __syncthreads();
    const int k2 = blockIdx.y * 32 + tx;
    #pragma unroll
    for (int m = 0; m < 32; m += 8) {
        const int j2 = blockIdx.x * 32 + ty + m;
        if (j2 < H && k2 < H)
            dst[(size_t)j2 * H + k2] = t[tx][ty + m];
    }
}

// ---------------------------------------------------------------------------
// Kernel 2: FUSED marginals, materialized T.
// GRID SWAPPED: grid=(2,400) — both halves of the same i are adjacent
// in block-linearization so X/XT slices are L2-shared between them.
// ---------------------------------------------------------------------------
__global__ __launch_bounds__(256, 2)
void kMargF(const float* __restrict__ X, const float* __restrict__ XT,
            const float* __restrict__ T,
            float* __restrict__ rowsOut, float* __restrict__ colsOut,
            const float* __restrict__ bias)
{
    extern __shared__ float sm[];
    float4* s4 = reinterpret_cast<float4*>(sm);   // [2][3072] f4

    const int i    = blockIdx.y;       // swapped
    const int half = blockIdx.x;       // swapped
    const int tid  = threadIdx.x;
    const int ks = tid & 15;
    const int tt = tid >> 4;
    const int nt = (tt & 3) * 4;
    const int ot = (tt >> 2) * 4;

    auto issue = [&](int ch) {
        const int q0 = ch * 16;
        const int full = (ch < 6);
        const int cq = full ? 16 : 4;
        float4* dX = s4 + (ch & 1) * 3072;
        float4* dY = dX + 1024;
        float4* dT = dY + 1024;
        for (int idx = tid; idx < 64 * cq; idx += 256) {
            const int r  = full ? (idx >> 4) : (idx >> 2);
            const int q2 = full ? (idx & 15) : (idx & 3);
            const int c = r >> 4, m = r & 15;
            const size_t off = (((size_t)(m * 4 + c)) * H + i) * H + (q0 + q2) * 4;
            cp16(&dX[r * 16 + q2], &X [off]);
            cp16(&dY[r * 16 + q2], &XT[off]);
            cp16(&dT[r * 16 + q2],
                 &T[((((size_t)(half * 16 + m)) * CC + c) * H + i) * H + (q0 + q2) * 4]);
        }
        cp_commit();
    };

    float accR[4][4] = {};
    float accC[4][4] = {};

    issue(0);
    #pragma unroll 1
    for (int ch = 0; ch < 7; ch++) {
        if (ch + 1 < 7) { issue(ch + 1); cp_wait<1>(); }
        else            { cp_wait<0>(); }
        __syncthreads();

        const int cq = (ch < 6) ? 16 : 4;
        const float4* bX = s4 + (ch & 1) * 3072;
        const float4* bY = bX + 1024;
        const float4* bT = bY + 1024;
        if (ks < cq) {
            #pragma unroll
            for (int c = 0; c < 4; c++) {
                float4 tv[4], xv[4], yv[4];
                #pragma unroll
                for (int b = 0; b < 4; b++) tv[b] = bT[(c * 16 + ot + b) * 16 + ks];
                #pragma unroll
                for (int a = 0; a < 4; a++) xv[a] = bX[(c * 16 + nt + a) * 16 + ks];
                #pragma unroll
                for (int a = 0; a < 4; a++) yv[a] = bY[(c * 16 + nt + a) * 16 + ks];
                #pragma unroll
                for (int a = 0; a < 4; a++)
                    #pragma unroll
                    for (int b = 0; b < 4; b++) {
                        accR[a][b] += dot4(xv[a], tv[b]);
                        accC[a][b] += dot4(yv[a], tv[b]);
                    }
            }
        }
        __syncthreads();
    }

    float* red = sm;    // 4096 floats
    const int tt2 = tid >> 4, ab = tid & 15;
    const int a2 = ab >> 2, b2 = ab & 3;
    const int n2  = (tt2 & 3) * 4 + a2;
    const int op2 = (tt2 >> 2) * 4 + b2;
    const int o2  = half * 16 + op2;

    #pragma unroll
    for (int a = 0; a < 4; a++)
        #pragma unroll
        for (int b = 0; b < 4; b++)
            red[(tt * 16 + a * 4 + b) * 16 + ks] = accR[a][b];
    __syncthreads();
    {
        float v = 0.f;
        #pragma unroll
        for (int s2 = 0; s2 < 16; s2++) v += red[tid * 16 + s2];
        v += bias[o2];
        rowsOut[((size_t)n2 * OO + o2) * H + i] = v;
    }
    __syncthreads();
    #pragma unroll
    for (int a = 0; a < 4; a++)
        #pragma unroll
        for (int b = 0; b < 4; b++)
            red[(tt * 16 + a * 4 + b) * 16 + ks] = accC[a][b];
    __syncthreads();
    {
        float v = 0.f;
        #pragma unroll
        for (int s2 = 0; s2 < 16; s2++) v += red[tid * 16 + s2];
        colsOut[((size_t)n2 * OO + o2) * H + i] = v;
    }
}

// ---------------------------------------------------------------------------
// Kernel 3: kOut, 512 threads, 1 n per thread.
// GRID SWAPPED: grid=(4,400) — the 4 o-groups of the same i are adjacent
// in block-linearization so the shared X slice is L2-served (one DRAM read).
// ---------------------------------------------------------------------------
__global__ __launch_bounds__(512, 2)
void kOut(const float* __restrict__ X, const float* __restrict__ T,
          const float* __restrict__ rows, const float* __restrict__ cols,
          float* __restrict__ out)
{
    extern __shared__ float sm[];
    float4* s4 = reinterpret_cast<float4*>(sm);   // [2][1024] f4 (T stages)
    float*  sr = sm + 2 * 1024 * 4;               // 128 floats

    const int i   = blockIdx.y;                   // swapped
    const int o0  = blockIdx.x * 8;               // swapped
    const int tid = threadIdx.x;

    if (tid < 128) {
        const int n = tid >> 3, op = tid & 7;
        sr[tid] = rows[((size_t)n * OO + o0 + op) * H + i];
    }

    auto issue = [&](int ch) {
        const int q0 = ch * 32;
        const int full = (ch < 3);
        const int cq = full ? 32 : 4;
        float4* dT = s4 + (ch & 1) * 1024;
        for (int idx = tid; idx < 32 * cq; idx += 512) {
            const int r  = full ? (idx >> 5) : (idx >> 2);
            const int q2 = full ? (idx & 31) : (idx & 3);
            const int c = r >> 3, op = r & 7;
            cp16(&dT[r * 32 + q2],
                 &T[((((size_t)(o0 + op)) * CC + c) * H + i) * H + (q0 + q2) * 4]);
        }
        cp_commit();
    };

    const int n = tid >> 5;      // one n per thread (0..15)
    const int q = tid & 31;      // quad lane

    issue(0);
    #pragma unroll 1
    for (int ch = 0; ch < 4; ch++) {
        if (ch + 1 < 4) { issue(ch + 1); cp_wait<1>(); }
        else            { cp_wait<0>(); }
        __syncthreads();

        const int q0 = ch * 32;
        const int cq = (ch < 3) ? 32 : 4;
        const float4* bT = s4 + (ch & 1) * 1024;

        if (q < cq) {
            float4 xv[4];
            #pragma unroll
            for (int c = 0; c < 4; c++)
                xv[c] = __ldg(reinterpret_cast<const float4*>(
                    &X[(((size_t)(n * 4 + c)) * H + i) * H + (q0 + q) * 4]));

            #pragma unroll
            for (int op = 0; op < 8; op++) {
                float4 tv[4];
                #pragma unroll
                for (int c = 0; c < 4; c++) tv[c] = bT[(c * 8 + op) * 32 + q];

                const int o = o0 + op;
                float4 cv = __ldg(reinterpret_cast<const float4*>(
                    &cols[((size_t)n * OO + o) * H + (q0 + q) * 4]));
                const float base = sr[n * 8 + op];
                float4 av;
                av.x = base + cv.x;
                av.y = base + cv.y;
                av.z = base + cv.z;
                av.w = base + cv.w;
                #pragma unroll
                for (int c = 0; c < 4; c++) {
                    av.x -= xv[c].x * tv[c].x;
                    av.y -= xv[c].y * tv[c].y;
                    av.z -= xv[c].z * tv[c].z;
                    av.w -= xv[c].w * tv[c].w;
                }
                *reinterpret_cast<float4*>(
                    &out[(((size_t)n * OO + o) * H + i) * H + (q0 + q) * 4]) = av;
            }
        }
        __syncthreads();
    }
}

// ---------------------------------------------------------------------------
extern "C" void kernel_launch(void* const* d_in, const int* in_sizes, int n_in,
                              void* d_out, int out_size)
{
    const float* x    = (const float*)d_in[0];
    const float* wL   = (const float*)d_in[1];
    const float* bias = (const float*)d_in[2];
    float*       out  = (float*)d_out;

    float *Tbuf, *XTbuf, *rowsBuf, *colsBuf;
    cudaGetSymbolAddress((void**)&Tbuf,    g_T);
    cudaGetSymbolAddress((void**)&XTbuf,   g_XT);
    cudaGetSymbolAddress((void**)&rowsBuf, g_rows);
    cudaGetSymbolAddress((void**)&colsBuf, g_cols);

    const int smMarg = 2 * 3072 * sizeof(float4);              // 98304
    const int smOut  = 2 * 1024 * sizeof(float4) + 128 * 4;    // 33280
    cudaFuncSetAttribute(kMargF, cudaFuncAttributeMaxDynamicSharedMemorySize, smMarg);
    cudaFuncSetAttribute(kOut,   cudaFuncAttributeMaxDynamicSharedMemorySize, smOut);

    kT<<<dim3(OO * CC, 16), 256>>>(wL, Tbuf);
    kTrans<<<dim3(13, 13, NN * CC), 256>>>(x, XTbuf);

    // grid dims swapped: same-i blocks adjacent => L2 reuse of X/XT slices
    kMargF<<<dim3(2, H), 256, smMarg>>>(x, XTbuf, Tbuf, rowsBuf, colsBuf, bias);

    kOut<<<dim3(4, H), 512, smOut>>>(x, Tbuf, rowsBuf, colsBuf, out);
}

// round 14
// speedup vs baseline: 1.0645x; 1.0645x over previous
#include <cuda_runtime.h>
#include <cstddef>
#include <cstdint>

#define H    400
#define CC   4
#define NN   16
#define OO   32
#define RR   4
#define HH   (H*H)          // 160000

// Static device scratch
__device__ float g_T [(size_t)OO*CC*HH];   // 81.92 MB : T[o][c][i][j]
__device__ float g_XT[(size_t)NN*CC*HH];   // 40.96 MB : XT[n][c][j][k]
__device__ float g_rows[NN*OO*H];
__device__ float g_cols[NN*OO*H];

// ---- cp.async helpers ------------------------------------------------------
__device__ __forceinline__ void cp16(void* smem_dst, const void* gmem_src) {
    uint32_t d = (uint32_t)__cvta_generic_to_shared(smem_dst);
    asm volatile("cp.async.cg.shared.global [%0], [%1], 16;\n" :: "r"(d), "l"(gmem_src));
}
__device__ __forceinline__ void cp_commit() {
    asm volatile("cp.async.commit_group;\n");
}
template<int N>
__device__ __forceinline__ void cp_wait() {
    asm volatile("cp.async.wait_group %0;\n" :: "n"(N));
}
__device__ __forceinline__ float dot4(float4 a, float4 b) {
    return a.x*b.x + a.y*b.y + a.z*b.z + a.w*b.w;
}

// ---------------------------------------------------------------------------
// Kernel 1a: T[o,c,i,j] = sum_r L[o,c,i,r]*L[o,c,j,r].  grid=(128,16), blk 256
// ---------------------------------------------------------------------------
__global__ __launch_bounds__(256)
void kT(const float* __restrict__ L, float* __restrict__ T)
{
    const int s = blockIdx.x;                 // o*CC + c
    const float* Lp = L + (size_t)s * (H*RR);
    float*       Tp = T + (size_t)s * HH;

    __shared__ float sL[H*RR];
    for (int idx = threadIdx.x; idx < H*RR; idx += 256) sL[idx] = Lp[idx];
    __syncthreads();

    const int base = blockIdx.y * 625;
    for (int loc = threadIdx.x; loc < 625; loc += 256) {
        const int item = base + loc;
        const int it = item / 100;
        const int jq = item % 100;
        const int i0 = it * 4, j0 = jq * 4;

        float4 li[4], lj[4];
        #pragma unroll
        for (int d = 0; d < 4; d++) {
            li[d] = *reinterpret_cast<const float4*>(&sL[(i0 + d) * 4]);
            lj[d] = *reinterpret_cast<const float4*>(&sL[(j0 + d) * 4]);
        }
        #pragma unroll
        for (int d = 0; d < 4; d++) {
            float4 v;
            v.x = dot4(li[d], lj[0]);
            v.y = dot4(li[d], lj[1]);
            v.z = dot4(li[d], lj[2]);
            v.w = dot4(li[d], lj[3]);
            *reinterpret_cast<float4*>(&Tp[(size_t)(i0 + d) * H + j0]) = v;
        }
    }
}

// ---------------------------------------------------------------------------
// Kernel 1b: per-(n,c) transpose XT[j,k] = x[k,j].  grid=(13,13,64), blk 256 flat
// ---------------------------------------------------------------------------
__global__ __launch_bounds__(256)
void kTrans(const float* __restrict__ X, float* __restrict__ XT)
{
    __shared__ float t[32][33];
    const int s = blockIdx.z;
    const float* src = X  + (size_t)s * HH;
    float*       dst = XT + (size_t)s * HH;
    const int tx = threadIdx.x & 31;
    const int ty = threadIdx.x >> 5;

    const int j = blockIdx.x * 32 + tx;
    #pragma unroll
    for (int m = 0; m < 32; m += 8) {
        const int k = blockIdx.y * 32 + ty + m;
        if (k < H && j < H)
            t[ty + m][tx] = src[(size_t)k * H + j];
    }
    __syncthreads();
    const int k2 = blockIdx.y * 32 + tx;
    #pragma unroll
    for (int m = 0; m < 32; m += 8) {
        const int j2 = blockIdx.x * 32 + ty + m;
        if (j2 < H && k2 < H)
            dst[(size_t)j2 * H + k2] = t[tx][ty + m];
    }
}

// ---------------------------------------------------------------------------
// Kernel 2: FUSED marginals (R11-proven, grid=(H,2) i-fastest).
// ---------------------------------------------------------------------------
__global__ __launch_bounds__(256, 2)
void kMargF(const float* __restrict__ X, const float* __restrict__ XT,
            const float* __restrict__ T,
            float* __restrict__ rowsOut, float* __restrict__ colsOut,
            const float* __restrict__ bias)
{
    extern __shared__ float sm[];
    float4* s4 = reinterpret_cast<float4*>(sm);   // [2][3072] f4

    const int i    = blockIdx.x;
    const int half = blockIdx.y;
    const int tid  = threadIdx.x;
    const int ks = tid & 15;
    const int tt = tid >> 4;
    const int nt = (tt & 3) * 4;
    const int ot = (tt >> 2) * 4;

    auto issue = [&](int ch) {
        const int q0 = ch * 16;
        const int full = (ch < 6);
        const int cq = full ? 16 : 4;
        float4* dX = s4 + (ch & 1) * 3072;
        float4* dY = dX + 1024;
        float4* dT = dY + 1024;
        for (int idx = tid; idx < 64 * cq; idx += 256) {
            const int r  = full ? (idx >> 4) : (idx >> 2);
            const int q2 = full ? (idx & 15) : (idx & 3);
            const int c = r >> 4, m = r & 15;
            const size_t off = (((size_t)(m * 4 + c)) * H + i) * H + (q0 + q2) * 4;
            cp16(&dX[r * 16 + q2], &X [off]);
            cp16(&dY[r * 16 + q2], &XT[off]);
            cp16(&dT[r * 16 + q2],
                 &T[((((size_t)(half * 16 + m)) * CC + c) * H + i) * H + (q0 + q2) * 4]);
        }
        cp_commit();
    };

    float accR[4][4] = {};
    float accC[4][4] = {};

    issue(0);
    #pragma unroll 1
    for (int ch = 0; ch < 7; ch++) {
        if (ch + 1 < 7) { issue(ch + 1); cp_wait<1>(); }
        else            { cp_wait<0>(); }
        __syncthreads();

        const int cq = (ch < 6) ? 16 : 4;
        const float4* bX = s4 + (ch & 1) * 3072;
        const float4* bY = bX + 1024;
        const float4* bT = bY + 1024;
        if (ks < cq) {
            #pragma unroll
            for (int c = 0; c < 4; c++) {
                float4 tv[4], xv[4], yv[4];
                #pragma unroll
                for (int b = 0; b < 4; b++) tv[b] = bT[(c * 16 + ot + b) * 16 + ks];
                #pragma unroll
                for (int a = 0; a < 4; a++) xv[a] = bX[(c * 16 + nt + a) * 16 + ks];
                #pragma unroll
                for (int a = 0; a < 4; a++) yv[a] = bY[(c * 16 + nt + a) * 16 + ks];
                #pragma unroll
                for (int a = 0; a < 4; a++)
                    #pragma unroll
                    for (int b = 0; b < 4; b++) {
                        accR[a][b] += dot4(xv[a], tv[b]);
                        accC[a][b] += dot4(yv[a], tv[b]);
                    }
            }
        }
        __syncthreads();
    }

    float* red = sm;    // 4096 floats
    const int tt2 = tid >> 4, ab = tid & 15;
    const int a2 = ab >> 2, b2 = ab & 3;
    const int n2  = (tt2 & 3) * 4 + a2;
    const int op2 = (tt2 >> 2) * 4 + b2;
    const int o2  = half * 16 + op2;

    #pragma unroll
    for (int a = 0; a < 4; a++)
        #pragma unroll
        for (int b = 0; b < 4; b++)
            red[(tt * 16 + a * 4 + b) * 16 + ks] = accR[a][b];
    __syncthreads();
    {
        float v = 0.f;
        #pragma unroll
        for (int s2 = 0; s2 < 16; s2++) v += red[tid * 16 + s2];
        v += bias[o2];
        rowsOut[((size_t)n2 * OO + o2) * H + i] = v;
    }
    __syncthreads();
    #pragma unroll
    for (int a = 0; a < 4; a++)
        #pragma unroll
        for (int b = 0; b < 4; b++)
            red[(tt * 16 + a * 4 + b) * 16 + ks] = accC[a][b];
    __syncthreads();
    {
        float v = 0.f;
        #pragma unroll
        for (int s2 = 0; s2 < 16; s2++) v += red[tid * 16 + s2];
        colsOut[((size_t)n2 * OO + o2) * H + i] = v;
    }
}

// ---------------------------------------------------------------------------
// Kernel 3: kOut — ONE BLOCK PER i, all 32 o.  grid=400, block 256.
// thread = (np = tid>>5 : n-pair, q = tid&31 : quad lane).
// T staged per (q-chunk, o-half): 8 stages of 64 rows x 32 q = 2048 f4 (32 KB),
// double-buffered [2][2048].  X read once per block; 512B warp stores.
// ---------------------------------------------------------------------------
__global__ __launch_bounds__(256, 3)
void kOut(const float* __restrict__ X, const float* __restrict__ T,
          const float* __restrict__ rows, const float* __restrict__ cols,
          float* __restrict__ out)
{
    extern __shared__ float sm[];
    float4* s4 = reinterpret_cast<float4*>(sm);   // [2][2048] f4 (T stages)
    float*  sr = sm + 2 * 2048 * 4;               // 512 floats (rows, all n,o)

    const int i   = blockIdx.x;
    const int tid = threadIdx.x;

    for (int p = tid; p < 512; p += 256) {
        const int n = p >> 5, o = p & 31;
        sr[p] = rows[((size_t)n * OO + o) * H + i];
    }

    // stage st = qc*2 + s : q-chunk qc (0..3), o-half s (0..1)
    auto issueT = [&](int st) {
        const int qc = st >> 1, s = st & 1;
        const int q0 = qc * 32;
        const int full = (qc < 3);
        const int cq = full ? 32 : 4;
        float4* dT = s4 + (st & 1) * 2048;
        for (int idx = tid; idx < 64 * cq; idx += 256) {
            const int r  = full ? (idx >> 5) : (idx >> 2);
            const int q2 = full ? (idx & 31) : (idx & 3);
            const int c = r >> 4, oo = r & 15;
            const int o = s * 16 + oo;
            cp16(&dT[r * 32 + q2],
                 &T[(((size_t)o * CC + c) * H + i) * H + (q0 + q2) * 4]);
        }
        cp_commit();
    };

    const int np = tid >> 5;
    const int q  = tid & 31;
    const int n0 = np * 2;

    float4 xv[2][4];

    issueT(0);
    #pragma unroll 1
    for (int st = 0; st < 8; st++) {
        if (st + 1 < 8) { issueT(st + 1); cp_wait<1>(); }
        else            { cp_wait<0>(); }
        __syncthreads();

        const int qc = st >> 1, s = st & 1;
        const int q0 = qc * 32;
        const int cq = (qc < 3) ? 32 : 4;
        const float4* bT = s4 + (st & 1) * 2048;

        if (q < cq) {
            if (s == 0) {   // new q-chunk: load X once, reuse for both o-halves
                #pragma unroll
                for (int d = 0; d < 2; d++)
                    #pragma unroll
                    for (int c = 0; c < 4; c++)
                        xv[d][c] = __ldg(reinterpret_cast<const float4*>(
                            &X[(((size_t)((n0 + d) * 4 + c)) * H + i) * H + (q0 + q) * 4]));
            }
            #pragma unroll 4
            for (int oo = 0; oo < 16; oo++) {
                const int o = s * 16 + oo;
                float4 tv[4];
                #pragma unroll
                for (int c = 0; c < 4; c++) tv[c] = bT[(c * 16 + oo) * 32 + q];

                #pragma unroll
                for (int d = 0; d < 2; d++) {
                    const int n = n0 + d;
                    float4 cv = __ldg(reinterpret_cast<const float4*>(
                        &cols[((size_t)n * OO + o) * H + (q0 + q) * 4]));
                    const float base = sr[n * 32 + o];
                    float4 av;
                    av.x = base + cv.x;
                    av.y = base + cv.y;
                    av.z = base + cv.z;
                    av.w = base + cv.w;
                    #pragma unroll
                    for (int c = 0; c < 4; c++) {
                        av.x -= xv[d][c].x * tv[c].x;
                        av.y -= xv[d][c].y * tv[c].y;
                        av.z -= xv[d][c].z * tv[c].z;
                        av.w -= xv[d][c].w * tv[c].w;
                    }
                    *reinterpret_cast<float4*>(
                        &out[(((size_t)n * OO + o) * H + i) * H + (q0 + q) * 4]) = av;
                }
            }
        }
        __syncthreads();
    }
}

// ---------------------------------------------------------------------------
extern "C" void kernel_launch(void* const* d_in, const int* in_sizes, int n_in,
                              void* d_out, int out_size)
{
    const float* x    = (const float*)d_in[0];
    const float* wL   = (const float*)d_in[1];
    const float* bias = (const float*)d_in[2];
    float*       out  = (float*)d_out;

    float *Tbuf, *XTbuf, *rowsBuf, *colsBuf;
    cudaGetSymbolAddress((void**)&Tbuf,    g_T);
    cudaGetSymbolAddress((void**)&XTbuf,   g_XT);
    cudaGetSymbolAddress((void**)&rowsBuf, g_rows);
    cudaGetSymbolAddress((void**)&colsBuf, g_cols);

    const int smMarg = 2 * 3072 * sizeof(float4);              // 98304
    const int smOut  = 2 * 2048 * sizeof(float4) + 512 * 4;    // 67584
    cudaFuncSetAttribute(kMargF, cudaFuncAttributeMaxDynamicSharedMemorySize, smMarg);
    cudaFuncSetAttribute(kOut,   cudaFuncAttributeMaxDynamicSharedMemorySize, smOut);

    kT<<<dim3(OO * CC, 16), 256>>>(wL, Tbuf);
    kTrans<<<dim3(13, 13, NN * CC), 256>>>(x, XTbuf);

    kMargF<<<dim3(H, 2), 256, smMarg>>>(x, XTbuf, Tbuf, rowsBuf, colsBuf, bias);

    kOut<<<H, 256, smOut>>>(x, Tbuf, rowsBuf, colsBuf, out);
}

// round 15
// speedup vs baseline: 1.0813x; 1.0158x over previous
#include <cuda_runtime.h>
#include <cstddef>
#include <cstdint>

#define H    400
#define CC   4
#define NN   16
#define OO   32
#define RR   4
#define HH   (H*H)          // 160000

// Static device scratch
__device__ float g_T [(size_t)OO*CC*HH];   // 81.92 MB : T[o][c][i][j]
__device__ float g_XT[(size_t)NN*CC*HH];   // 40.96 MB : XT[n][c][j][k]
__device__ float g_rows[NN*OO*H];
__device__ float g_cols[NN*OO*H];

// ---- cp.async helpers ------------------------------------------------------
__device__ __forceinline__ void cp16(void* smem_dst, const void* gmem_src) {
    uint32_t d = (uint32_t)__cvta_generic_to_shared(smem_dst);
    asm volatile("cp.async.cg.shared.global [%0], [%1], 16;\n" :: "r"(d), "l"(gmem_src));
}
__device__ __forceinline__ void cp_commit() {
    asm volatile("cp.async.commit_group;\n");
}
template<int N>
__device__ __forceinline__ void cp_wait() {
    asm volatile("cp.async.wait_group %0;\n" :: "n"(N));
}
__device__ __forceinline__ float dot4(float4 a, float4 b) {
    return a.x*b.x + a.y*b.y + a.z*b.z + a.w*b.w;
}

// ---------------------------------------------------------------------------
// Kernel 1a: T[o,c,i,j] = sum_r L[o,c,i,r]*L[o,c,j,r].  grid=(128,16), blk 256
// ---------------------------------------------------------------------------
__global__ __launch_bounds__(256)
void kT(const float* __restrict__ L, float* __restrict__ T)
{
    const int s = blockIdx.x;                 // o*CC + c
    const float* Lp = L + (size_t)s * (H*RR);
    float*       Tp = T + (size_t)s * HH;

    __shared__ float sL[H*RR];
    for (int idx = threadIdx.x; idx < H*RR; idx += 256) sL[idx] = Lp[idx];
    __syncthreads();

    const int base = blockIdx.y * 625;
    for (int loc = threadIdx.x; loc < 625; loc += 256) {
        const int item = base + loc;
        const int it = item / 100;
        const int jq = item % 100;
        const int i0 = it * 4, j0 = jq * 4;

        float4 li[4], lj[4];
        #pragma unroll
        for (int d = 0; d < 4; d++) {
            li[d] = *reinterpret_cast<const float4*>(&sL[(i0 + d) * 4]);
            lj[d] = *reinterpret_cast<const float4*>(&sL[(j0 + d) * 4]);
        }
        #pragma unroll
        for (int d = 0; d < 4; d++) {
            float4 v;
            v.x = dot4(li[d], lj[0]);
            v.y = dot4(li[d], lj[1]);
            v.z = dot4(li[d], lj[2]);
            v.w = dot4(li[d], lj[3]);
            *reinterpret_cast<float4*>(&Tp[(size_t)(i0 + d) * H + j0]) = v;
        }
    }
}

// ---------------------------------------------------------------------------
// Kernel 1b: per-(n,c) transpose XT[j,k] = x[k,j].  grid=(13,13,64), blk 256 flat
// ---------------------------------------------------------------------------
__global__ __launch_bounds__(256)
void kTrans(const float* __restrict__ X, float* __restrict__ XT)
{
    __shared__ float t[32][33];
    const int s = blockIdx.z;
    const float* src = X  + (size_t)s * HH;
    float*       dst = XT + (size_t)s * HH;
    const int tx = threadIdx.x & 31;
    const int ty = threadIdx.x >> 5;

    const int j = blockIdx.x * 32 + tx;
    #pragma unroll
    for (int m = 0; m < 32; m += 8) {
        const int k = blockIdx.y * 32 + ty + m;
        if (k < H && j < H)
            t[ty + m][tx] = src[(size_t)k * H + j];
    }
    __syncthreads();
    const int k2 = blockIdx.y * 32 + tx;
    #pragma unroll
    for (int m = 0; m < 32; m += 8) {
        const int j2 = blockIdx.x * 32 + ty + m;
        if (j2 < H && k2 < H)
            dst[(size_t)j2 * H + k2] = t[tx][ty + m];
    }
}

// ---------------------------------------------------------------------------
// Kernel 2: FUSED marginals (R11-proven, grid=(H,2) i-fastest).
// ---------------------------------------------------------------------------
__global__ __launch_bounds__(256, 2)
void kMargF(const float* __restrict__ X, const float* __restrict__ XT,
            const float* __restrict__ T,
            float* __restrict__ rowsOut, float* __restrict__ colsOut,
            const float* __restrict__ bias)
{
    extern __shared__ float sm[];
    float4* s4 = reinterpret_cast<float4*>(sm);   // [2][3072] f4

    const int i    = blockIdx.x;
    const int half = blockIdx.y;
    const int tid  = threadIdx.x;
    const int ks = tid & 15;
    const int tt = tid >> 4;
    const int nt = (tt & 3) * 4;
    const int ot = (tt >> 2) * 4;

    auto issue = [&](int ch) {
        const int q0 = ch * 16;
        const int full = (ch < 6);
        const int cq = full ? 16 : 4;
        float4* dX = s4 + (ch & 1) * 3072;
        float4* dY = dX + 1024;
        float4* dT = dY + 1024;
        for (int idx = tid; idx < 64 * cq; idx += 256) {
            const int r  = full ? (idx >> 4) : (idx >> 2);
            const int q2 = full ? (idx & 15) : (idx & 3);
            const int c = r >> 4, m = r & 15;
            const size_t off = (((size_t)(m * 4 + c)) * H + i) * H + (q0 + q2) * 4;
            cp16(&dX[r * 16 + q2], &X [off]);
            cp16(&dY[r * 16 + q2], &XT[off]);
            cp16(&dT[r * 16 + q2],
                 &T[((((size_t)(half * 16 + m)) * CC + c) * H + i) * H + (q0 + q2) * 4]);
        }
        cp_commit();
    };

    float accR[4][4] = {};
    float accC[4][4] = {};

    issue(0);
    #pragma unroll 1
    for (int ch = 0; ch < 7; ch++) {
        if (ch + 1 < 7) { issue(ch + 1); cp_wait<1>(); }
        else            { cp_wait<0>(); }
        __syncthreads();

        const int cq = (ch < 6) ? 16 : 4;
        const float4* bX = s4 + (ch & 1) * 3072;
        const float4* bY = bX + 1024;
        const float4* bT = bY + 1024;
        if (ks < cq) {
            #pragma unroll
            for (int c = 0; c < 4; c++) {
                float4 tv[4], xv[4], yv[4];
                #pragma unroll
                for (int b = 0; b < 4; b++) tv[b] = bT[(c * 16 + ot + b) * 16 + ks];
                #pragma unroll
                for (int a = 0; a < 4; a++) xv[a] = bX[(c * 16 + nt + a) * 16 + ks];
                #pragma unroll
                for (int a = 0; a < 4; a++) yv[a] = bY[(c * 16 + nt + a) * 16 + ks];
                #pragma unroll
                for (int a = 0; a < 4; a++)
                    #pragma unroll
                    for (int b = 0; b < 4; b++) {
                        accR[a][b] += dot4(xv[a], tv[b]);
                        accC[a][b] += dot4(yv[a], tv[b]);
                    }
            }
        }
        __syncthreads();
    }

    float* red = sm;    // 4096 floats
    const int tt2 = tid >> 4, ab = tid & 15;
    const int a2 = ab >> 2, b2 = ab & 3;
    const int n2  = (tt2 & 3) * 4 + a2;
    const int op2 = (tt2 >> 2) * 4 + b2;
    const int o2  = half * 16 + op2;

    #pragma unroll
    for (int a = 0; a < 4; a++)
        #pragma unroll
        for (int b = 0; b < 4; b++)
            red[(tt * 16 + a * 4 + b) * 16 + ks] = accR[a][b];
    __syncthreads();
    {
        float v = 0.f;
        #pragma unroll
        for (int s2 = 0; s2 < 16; s2++) v += red[tid * 16 + s2];
        v += bias[o2];
        rowsOut[((size_t)n2 * OO + o2) * H + i] = v;
    }
    __syncthreads();
    #pragma unroll
    for (int a = 0; a < 4; a++)
        #pragma unroll
        for (int b = 0; b < 4; b++)
            red[(tt * 16 + a * 4 + b) * 16 + ks] = accC[a][b];
    __syncthreads();
    {
        float v = 0.f;
        #pragma unroll
        for (int s2 = 0; s2 < 16; s2++) v += red[tid * 16 + s2];
        colsOut[((size_t)n2 * OO + o2) * H + i] = v;
    }
}

// ---------------------------------------------------------------------------
// Kernel 3: kOut — one block per i, all 32 o, 512 THREADS (1 n per thread).
// grid=400, block 512.  thread = (n = tid>>5, q = tid&31).
// T staged per (q-chunk, o-half): 8 stages of 64 rows x 32 q (32 KB), 2-buf.
// X read once per block; regs ~64 -> 2 blocks/SM = 32 warps (occ 50%).
// ---------------------------------------------------------------------------
__global__ __launch_bounds__(512, 2)
void kOut(const float* __restrict__ X, const float* __restrict__ T,
          const float* __restrict__ rows, const float* __restrict__ cols,
          float* __restrict__ out)
{
    extern __shared__ float sm[];
    float4* s4 = reinterpret_cast<float4*>(sm);   // [2][2048] f4 (T stages)
    float*  sr = sm + 2 * 2048 * 4;               // 512 floats (rows, all n,o)

    const int i   = blockIdx.x;
    const int tid = threadIdx.x;

    if (tid < 512) {
        const int n = tid >> 5, o = tid & 31;
        sr[tid] = rows[((size_t)n * OO + o) * H + i];
    }

    // stage st = qc*2 + s : q-chunk qc (0..3), o-half s (0..1)
    auto issueT = [&](int st) {
        const int qc = st >> 1, s = st & 1;
        const int q0 = qc * 32;
        const int full = (qc < 3);
        const int cq = full ? 32 : 4;
        float4* dT = s4 + (st & 1) * 2048;
        for (int idx = tid; idx < 64 * cq; idx += 512) {
            const int r  = full ? (idx >> 5) : (idx >> 2);
            const int q2 = full ? (idx & 31) : (idx & 3);
            const int c = r >> 4, oo = r & 15;
            const int o = s * 16 + oo;
            cp16(&dT[r * 32 + q2],
                 &T[(((size_t)o * CC + c) * H + i) * H + (q0 + q2) * 4]);
        }
        cp_commit();
    };

    const int n = tid >> 5;      // one n per thread (0..15)
    const int q = tid & 31;      // quad lane

    float4 xv[4];

    issueT(0);
    #pragma unroll 1
    for (int st = 0; st < 8; st++) {
        if (st + 1 < 8) { issueT(st + 1); cp_wait<1>(); }
        else            { cp_wait<0>(); }
        __syncthreads();

        const int qc = st >> 1, s = st & 1;
        const int q0 = qc * 32;
        const int cq = (qc < 3) ? 32 : 4;
        const float4* bT = s4 + (st & 1) * 2048;

        if (q < cq) {
            if (s == 0) {   // new q-chunk: load X once, reuse for both o-halves
                #pragma unroll
                for (int c = 0; c < 4; c++)
                    xv[c] = __ldg(reinterpret_cast<const float4*>(
                        &X[(((size_t)(n * 4 + c)) * H + i) * H + (q0 + q) * 4]));
            }
            #pragma unroll 4
            for (int oo = 0; oo < 16; oo++) {
                const int o = s * 16 + oo;
                float4 tv[4];
                #pragma unroll
                for (int c = 0; c < 4; c++) tv[c] = bT[(c * 16 + oo) * 32 + q];

                float4 cv = __ldg(reinterpret_cast<const float4*>(
                    &cols[((size_t)n * OO + o) * H + (q0 + q) * 4]));
                const float base = sr[n * 32 + o];
                float4 av;
                av.x = base + cv.x;
                av.y = base + cv.y;
                av.z = base + cv.z;
                av.w = base + cv.w;
                #pragma unroll
                for (int c = 0; c < 4; c++) {
                    av.x -= xv[c].x * tv[c].x;
                    av.y -= xv[c].y * tv[c].y;
                    av.z -= xv[c].z * tv[c].z;
                    av.w -= xv[c].w * tv[c].w;
                }
                *reinterpret_cast<float4*>(
                    &out[(((size_t)n * OO + o) * H + i) * H + (q0 + q) * 4]) = av;
            }
        }
        __syncthreads();
    }
}

// ---------------------------------------------------------------------------
extern "C" void kernel_launch(void* const* d_in, const int* in_sizes, int n_in,
                              void* d_out, int out_size)
{
    const float* x    = (const float*)d_in[0];
    const float* wL   = (const float*)d_in[1];
    const float* bias = (const float*)d_in[2];
    float*       out  = (float*)d_out;

    float *Tbuf, *XTbuf, *rowsBuf, *colsBuf;
    cudaGetSymbolAddress((void**)&Tbuf,    g_T);
    cudaGetSymbolAddress((void**)&XTbuf,   g_XT);
    cudaGetSymbolAddress((void**)&rowsBuf, g_rows);
    cudaGetSymbolAddress((void**)&colsBuf, g_cols);

    const int smMarg = 2 * 3072 * sizeof(float4);              // 98304
    const int smOut  = 2 * 2048 * sizeof(float4) + 512 * 4;    // 67584
    cudaFuncSetAttribute(kMargF, cudaFuncAttributeMaxDynamicSharedMemorySize, smMarg);
    cudaFuncSetAttribute(kOut,   cudaFuncAttributeMaxDynamicSharedMemorySize, smOut);

    kT<<<dim3(OO * CC, 16), 256>>>(wL, Tbuf);
    kTrans<<<dim3(13, 13, NN * CC), 256>>>(x, XTbuf);

    kMargF<<<dim3(H, 2), 256, smMarg>>>(x, XTbuf, Tbuf, rowsBuf, colsBuf, bias);

    kOut<<<H, 512, smOut>>>(x, Tbuf, rowsBuf, colsBuf, out);
}